// round 3
// baseline (speedup 1.0000x reference)
#include <cuda_runtime.h>
#include <cuda_bf16.h>
#include <cstddef>

// Problem constants
#define NCH 16
#define ND  64
#define NH  96
#define NW  96
#define PLANE (NH*NW)            // 9216
#define CH_STRIDE (ND*NH*NW)     // 589824
#define KOUT 8

// Shared layout (floats):
// AB  : 36 rows x 38 cols of float2 (A,BZ)   = 2736 floats @ 0
// GX/GY/GZ : 34 rows x 36 cols               = 1224 each   @ 2736/3960/5184
// RP  : 2 buffers x 3 arrays x (34x34 float2)= 13872 floats @ 6408
// RED : 32                                                  @ 20280
#define OFF_G   2736
#define OFF_RP  6408
#define OFF_RED 20280
#define SH_FLOATS 20312
#define SH_BYTES  (SH_FLOATS*4)

#define RP_F2_PER_ARR 1156     // 34*34 float2
#define RP_F2_PER_BUF 3468     // 3 arrays

__device__ double g_p[NCH];
__device__ int    g_idx[KOUT];

__global__ void zero_kernel() {
    if (threadIdx.x < NCH) g_p[threadIdx.x] = 0.0;
}

__device__ __forceinline__ float harris_of(float sxx, float syy, float szz,
                                           float sxy, float sxz, float syz) {
    float det = sxx*(syy*szz - syz*syz)
              - sxy*(sxy*szz - syz*sxz)
              + sxz*(sxy*syz - syy*sxz);
    float tr  = sxx + syy + szz;
    const float C1 = 1.f/19683.f;       // 1/27^3
    const float C2 = 0.04f/729.f;       // k/27^2
    return det*C1 - C2*tr*tr;
}

__global__ __launch_bounds__(512, 2) void harris_kernel(const float* __restrict__ x) {
    extern __shared__ float sh[];
    float2* AB  = reinterpret_cast<float2*>(sh);          // (A, BZ) interleaved
    float*  GX  = sh + OFF_G;
    float*  GY  = GX + 1224;
    float*  GZ  = GY + 1224;
    float2* RPB[2];
    RPB[0] = reinterpret_cast<float2*>(sh + OFF_RP);
    RPB[1] = RPB[0] + RP_F2_PER_BUF;
    float*  RED = sh + OFF_RED;

    const int tid = threadIdx.x;
    const int c     = blockIdx.z >> 1;
    const int zhalf = blockIdx.z & 1;
    const int h0  = blockIdx.y * 32;
    const int w0  = blockIdx.x * 32;
    const float* xc = x + (size_t)c * CH_STRIDE;

    const int z0 = zhalf * 32;
    const int z1 = z0 + 32;
    const int s_begin = (z0 == 0) ? 0 : z0 - 1;
    const int s_end   = (z1 == ND) ? ND - 1 : z1;   // inclusive

    // ---- per-thread owned pixels of the 36x36 extended grid (up to 3) ----
    int offs[3];   // global plane offset or -1 (zero pad)
    int sto[3];    // AB store index (i*38+j) or -1
#pragma unroll
    for (int k = 0; k < 3; k++) {
        int idx = tid + k * 512;
        if (idx < 36*36) {
            int i = idx / 36, j = idx % 36;
            sto[k] = i*38 + j;
            int gh = h0 + i - 2, gw = w0 + j - 2;
            offs[k] = ((unsigned)gh < (unsigned)NH && (unsigned)gw < (unsigned)NW)
                      ? gh*NW + gw : -1;
        } else { sto[k] = -1; offs[k] = -1; }
    }

    // x-depth ring in registers: xm = x(t-1), x0r = x(t) for next st1(t)
    float xm[3], x0r[3];
#pragma unroll
    for (int k = 0; k < 3; k++) {
        xm[k] = 0.f; x0r[k] = 0.f;
        if (offs[k] >= 0) {
            if (s_begin - 1 >= 0) xm[k] = xc[(size_t)(s_begin-1)*PLANE + offs[k]];
            x0r[k] = xc[(size_t)s_begin*PLANE + offs[k]];
        }
    }

    // stage-2 mapping (2x2 patches, 289 threads)
    const int pi = tid / 17, pj = tid % 17;   // valid when tid < 289
    // stage-3 mapping (2-col items): idx -> i = idx>>4, jp = idx&15
    // stage-4 mapping: 2 output pixels per thread
    const int tw = tid & 31;
    const int r0 = (tid >> 5) * 2;
    const int base4 = r0*34 + tw;             // RP float2 index

    // depth running sums
    float A1[12], A2[12];
#pragma unroll
    for (int i = 0; i < 12; i++) { A1[i] = 0.f; A2[i] = 0.f; }
    float hsum = 0.f;

    // ================= prologue: st1(s_begin), st2(s_begin) =================
    {
        int t = s_begin;
#pragma unroll
        for (int k = 0; k < 3; k++) {
            if (sto[k] >= 0) {
                float xpv = (offs[k] >= 0 && t+1 < ND)
                            ? xc[(size_t)(t+1)*PLANE + offs[k]] : 0.f;
                AB[sto[k]] = make_float2(xm[k] + x0r[k] + xpv, xpv - xm[k]);
                xm[k] = x0r[k]; x0r[k] = xpv;
            }
        }
    }
    __syncthreads();

#define STAGE2() do {                                                          \
    if (tid < 289) {                                                           \
        int i0 = pi*2, j0 = pj*2;                                              \
        float Av[4][4], Bv[4][4];                                              \
        _Pragma("unroll")                                                      \
        for (int r = 0; r < 4; r++) {                                          \
            const float4* p = reinterpret_cast<const float4*>(AB + ((i0+r)*38 + j0)); \
            float4 u = p[0], v = p[1];                                         \
            Av[r][0]=u.x; Bv[r][0]=u.y; Av[r][1]=u.z; Bv[r][1]=u.w;            \
            Av[r][2]=v.x; Bv[r][2]=v.y; Av[r][3]=v.z; Bv[r][3]=v.w;            \
        }                                                                      \
        float hd[4][2], h121[4][2], rs[4][2];                                  \
        _Pragma("unroll")                                                      \
        for (int r = 0; r < 4; r++) {                                          \
            hd[r][0]   = Av[r][2] - Av[r][0];                                  \
            hd[r][1]   = Av[r][3] - Av[r][1];                                  \
            h121[r][0] = Av[r][0] + 2.f*Av[r][1] + Av[r][2];                   \
            h121[r][1] = Av[r][1] + 2.f*Av[r][2] + Av[r][3];                   \
            rs[r][0]   = Bv[r][0] + Bv[r][1] + Bv[r][2];                       \
            rs[r][1]   = Bv[r][1] + Bv[r][2] + Bv[r][3];                       \
        }                                                                      \
        _Pragma("unroll")                                                      \
        for (int rr = 0; rr < 2; rr++) {                                       \
            int go = (i0+rr)*36 + j0;                                          \
            float gx0 = hd[rr][0] + 2.f*hd[rr+1][0] + hd[rr+2][0];             \
            float gx1 = hd[rr][1] + 2.f*hd[rr+1][1] + hd[rr+2][1];             \
            float gy0 = h121[rr+2][0] - h121[rr][0];                           \
            float gy1 = h121[rr+2][1] - h121[rr][1];                           \
            float gz0 = rs[rr][0] + rs[rr+1][0] + rs[rr+2][0];                 \
            float gz1 = rs[rr][1] + rs[rr+1][1] + rs[rr+2][1];                 \
            *reinterpret_cast<float2*>(GX + go) = make_float2(gx0, gx1);       \
            *reinterpret_cast<float2*>(GY + go) = make_float2(gy0, gy1);       \
            *reinterpret_cast<float2*>(GZ + go) = make_float2(gz0, gz1);       \
        }                                                                      \
    }                                                                          \
} while (0)

#define STAGE3_ITEM(idx, RPa, RPb, RPc) do {                                   \
    int i = (idx) >> 4, jp = (idx) & 15;                                       \
    int b = i*36 + jp*2;                                                       \
    float2 xa = *reinterpret_cast<const float2*>(GX + b);                      \
    float2 xb = *reinterpret_cast<const float2*>(GX + b + 2);                  \
    float2 ya = *reinterpret_cast<const float2*>(GY + b);                      \
    float2 yb = *reinterpret_cast<const float2*>(GY + b + 2);                  \
    float2 za = *reinterpret_cast<const float2*>(GZ + b);                      \
    float2 zb = *reinterpret_cast<const float2*>(GZ + b + 2);                  \
    float X0[3] = {xa.x, xa.y, xb.x}, X1[3] = {xa.y, xb.x, xb.y};              \
    float Y0[3] = {ya.x, ya.y, yb.x}, Y1[3] = {ya.y, yb.x, yb.y};              \
    float Z0[3] = {za.x, za.y, zb.x}, Z1[3] = {za.y, zb.x, zb.y};              \
    float sxx0=0,syy0=0,szz0=0,sxy0=0,sxz0=0,syz0=0;                           \
    float sxx1=0,syy1=0,szz1=0,sxy1=0,sxz1=0,syz1=0;                           \
    _Pragma("unroll")                                                          \
    for (int tt = 0; tt < 3; tt++) {                                           \
        sxx0 = fmaf(X0[tt],X0[tt],sxx0); syy0 = fmaf(Y0[tt],Y0[tt],syy0);      \
        szz0 = fmaf(Z0[tt],Z0[tt],szz0); sxy0 = fmaf(X0[tt],Y0[tt],sxy0);      \
        sxz0 = fmaf(X0[tt],Z0[tt],sxz0); syz0 = fmaf(Y0[tt],Z0[tt],syz0);      \
        sxx1 = fmaf(X1[tt],X1[tt],sxx1); syy1 = fmaf(Y1[tt],Y1[tt],syy1);      \
        szz1 = fmaf(Z1[tt],Z1[tt],szz1); sxy1 = fmaf(X1[tt],Y1[tt],sxy1);      \
        sxz1 = fmaf(X1[tt],Z1[tt],sxz1); syz1 = fmaf(Y1[tt],Z1[tt],syz1);      \
    }                                                                          \
    int ro = i*34 + jp*2;                                                      \
    *reinterpret_cast<float4*>(RPa + ro) = make_float4(sxx0,syy0,sxx1,syy1);   \
    *reinterpret_cast<float4*>(RPb + ro) = make_float4(szz0,sxy0,szz1,sxy1);   \
    *reinterpret_cast<float4*>(RPc + ro) = make_float4(sxz0,sxz1... )          \
} while (0)

    // NOTE: macro above unused placeholder removed below; real code inline.
#undef STAGE3_ITEM

    STAGE2();
    __syncthreads();

    // ================= main loop =================
    for (int s = s_begin; s <= s_end; s++) {
        // ---------- phase A: st1 loads, st3(s), st4(s-1), st1 stores ----------
        const bool do_st1 = (s + 1 <= s_end);
        float xpv[3];
        if (do_st1) {
#pragma unroll
            for (int k = 0; k < 3; k++) {
                xpv[k] = 0.f;
                if (sto[k] >= 0 && offs[k] >= 0 && s + 2 < ND)
                    xpv[k] = xc[(size_t)(s+2)*PLANE + offs[k]];
            }
        }

        // st3(s) -> RPB[s&1]
        {
            float2* RPa = RPB[s & 1];
            float2* RPb = RPa + RP_F2_PER_ARR;
            float2* RPc = RPb + RP_F2_PER_ARR;
#pragma unroll
            for (int pass = 0; pass < 2; pass++) {
                int idx = tid + pass * 512;
                if (pass == 1 && tid >= 32) break;
                if (idx < 544) {
                    int i = idx >> 4, jp = idx & 15;
                    int b = i*36 + jp*2;
                    float2 xa = *reinterpret_cast<const float2*>(GX + b);
                    float2 xb = *reinterpret_cast<const float2*>(GX + b + 2);
                    float2 ya = *reinterpret_cast<const float2*>(GY + b);
                    float2 yb = *reinterpret_cast<const float2*>(GY + b + 2);
                    float2 za = *reinterpret_cast<const float2*>(GZ + b);
                    float2 zb = *reinterpret_cast<const float2*>(GZ + b + 2);
                    float sxx0=0,syy0=0,szz0=0,sxy0=0,sxz0=0,syz0=0;
                    float sxx1=0,syy1=0,szz1=0,sxy1=0,sxz1=0,syz1=0;
                    {
                        float X0[3] = {xa.x, xa.y, xb.x}, X1[3] = {xa.y, xb.x, xb.y};
                        float Y0[3] = {ya.x, ya.y, yb.x}, Y1[3] = {ya.y, yb.x, yb.y};
                        float Z0[3] = {za.x, za.y, zb.x}, Z1[3] = {za.y, zb.x, zb.y};
#pragma unroll
                        for (int tt = 0; tt < 3; tt++) {
                            sxx0 = fmaf(X0[tt],X0[tt],sxx0); syy0 = fmaf(Y0[tt],Y0[tt],syy0);
                            szz0 = fmaf(Z0[tt],Z0[tt],szz0); sxy0 = fmaf(X0[tt],Y0[tt],sxy0);
                            sxz0 = fmaf(X0[tt],Z0[tt],sxz0); syz0 = fmaf(Y0[tt],Z0[tt],syz0);
                            sxx1 = fmaf(X1[tt],X1[tt],sxx1); syy1 = fmaf(Y1[tt],Y1[tt],syy1);
                            szz1 = fmaf(Z1[tt],Z1[tt],szz1); sxy1 = fmaf(X1[tt],Y1[tt],sxy1);
                            sxz1 = fmaf(X1[tt],Z1[tt],sxz1); syz1 = fmaf(Y1[tt],Z1[tt],syz1);
                        }
                    }
                    int ro = i*34 + jp*2;
                    *reinterpret_cast<float4*>(RPa + ro) = make_float4(sxx0,syy0,sxx1,syy1);
                    *reinterpret_cast<float4*>(RPb + ro) = make_float4(szz0,sxy0,szz1,sxy1);
                    *reinterpret_cast<float4*>(RPc + ro) = make_float4(sxz0,syz0,sxz1,syz1);
                }
            }
        }

        // st1(s+1) stores (loads already in flight)
        if (do_st1) {
#pragma unroll
            for (int k = 0; k < 3; k++) {
                if (sto[k] >= 0) {
                    AB[sto[k]] = make_float2(xm[k] + x0r[k] + xpv[k], xpv[k] - xm[k]);
                    xm[k] = x0r[k]; x0r[k] = xpv[k];
                }
            }
        }

        // st4(s-1) from RPB[(s-1)&1]
        if (s > s_begin) {
            const int t = s - 1;
            float2* RPa = RPB[t & 1];
            float2* RPb = RPa + RP_F2_PER_ARR;
            float2* RPc = RPb + RP_F2_PER_ARR;
            float2 a0 = RPa[base4], a1 = RPa[base4+34], a2 = RPa[base4+68], a3 = RPa[base4+102];
            float2 b0 = RPb[base4], b1 = RPb[base4+34], b2 = RPb[base4+68], b3 = RPb[base4+102];
            float2 c0 = RPc[base4], c1 = RPc[base4+34], c2 = RPc[base4+68], c3 = RPc[base4+102];
            float cur[12];
            cur[0]  = a0.x + a1.x + a2.x;
            cur[1]  = a0.y + a1.y + a2.y;
            cur[2]  = b0.x + b1.x + b2.x;
            cur[3]  = b0.y + b1.y + b2.y;
            cur[4]  = c0.x + c1.x + c2.x;
            cur[5]  = c0.y + c1.y + c2.y;
            cur[6]  = a1.x + a2.x + a3.x;
            cur[7]  = a1.y + a2.y + a3.y;
            cur[8]  = b1.x + b2.x + b3.x;
            cur[9]  = b1.y + b2.y + b3.y;
            cur[10] = c1.x + c2.x + c3.x;
            cur[11] = c1.y + c2.y + c3.y;
            int d = t - 1;
            if (d >= z0 && d < z1) {
#pragma unroll
                for (int px = 0; px < 2; px++) {
                    hsum += harris_of(A2[px*6+0] + cur[px*6+0],
                                      A2[px*6+1] + cur[px*6+1],
                                      A2[px*6+2] + cur[px*6+2],
                                      A2[px*6+3] + cur[px*6+3],
                                      A2[px*6+4] + cur[px*6+4],
                                      A2[px*6+5] + cur[px*6+5]);
                }
            }
#pragma unroll
            for (int i = 0; i < 12; i++) { A2[i] = A1[i] + cur[i]; A1[i] = cur[i]; }
        }
        __syncthreads();

        // ---------- phase B: st2(s+1) ----------
        if (do_st1) {
            STAGE2();
        }
        __syncthreads();
    }

    // ================= epilogue: st4(s_end) + tail =================
    {
        const int t = s_end;
        float2* RPa = RPB[t & 1];
        float2* RPb = RPa + RP_F2_PER_ARR;
        float2* RPc = RPb + RP_F2_PER_ARR;
        float2 a0 = RPa[base4], a1 = RPa[base4+34], a2 = RPa[base4+68], a3 = RPa[base4+102];
        float2 b0 = RPb[base4], b1 = RPb[base4+34], b2 = RPb[base4+68], b3 = RPb[base4+102];
        float2 c0 = RPc[base4], c1 = RPc[base4+34], c2 = RPc[base4+68], c3 = RPc[base4+102];
        float cur[12];
        cur[0]  = a0.x + a1.x + a2.x;
        cur[1]  = a0.y + a1.y + a2.y;
        cur[2]  = b0.x + b1.x + b2.x;
        cur[3]  = b0.y + b1.y + b2.y;
        cur[4]  = c0.x + c1.x + c2.x;
        cur[5]  = c0.y + c1.y + c2.y;
        cur[6]  = a1.x + a2.x + a3.x;
        cur[7]  = a1.y + a2.y + a3.y;
        cur[8]  = b1.x + b2.x + b3.x;
        cur[9]  = b1.y + b2.y + b3.y;
        cur[10] = c1.x + c2.x + c3.x;
        cur[11] = c1.y + c2.y + c3.y;
        int d = t - 1;
        if (d >= z0 && d < z1) {
#pragma unroll
            for (int px = 0; px < 2; px++) {
                hsum += harris_of(A2[px*6+0] + cur[px*6+0],
                                  A2[px*6+1] + cur[px*6+1],
                                  A2[px*6+2] + cur[px*6+2],
                                  A2[px*6+3] + cur[px*6+3],
                                  A2[px*6+4] + cur[px*6+4],
                                  A2[px*6+5] + cur[px*6+5]);
            }
        }
#pragma unroll
        for (int i = 0; i < 12; i++) { A2[i] = A1[i] + cur[i]; A1[i] = cur[i]; }
    }
    if (z1 == ND) {
        // output depth ND-1: slice at ND contributes 0
#pragma unroll
        for (int px = 0; px < 2; px++) {
            hsum += harris_of(A2[px*6+0], A2[px*6+1], A2[px*6+2],
                              A2[px*6+3], A2[px*6+4], A2[px*6+5]);
        }
    }

    // ---- reduction ----
#pragma unroll
    for (int o = 16; o > 0; o >>= 1)
        hsum += __shfl_down_sync(0xffffffffu, hsum, o);
    if ((tid & 31) == 0) RED[tid >> 5] = hsum;
    __syncthreads();
    if (tid < 32) {
        float v = (tid < 16) ? RED[tid] : 0.f;
#pragma unroll
        for (int o = 8; o > 0; o >>= 1)
            v += __shfl_down_sync(0xffffffffu, v, o);
        if (tid == 0) atomicAdd(&g_p[c], (double)v);
    }
#undef STAGE2
}

__global__ void topk_kernel() {
    if (threadIdx.x == 0 && blockIdx.x == 0) {
        double v[NCH];
        bool used[NCH];
        for (int i = 0; i < NCH; i++) { v[i] = g_p[i]; used[i] = false; }
        for (int k = 0; k < KOUT; k++) {
            int bi = 0; double bv = -1e300; bool found = false;
            for (int i = 0; i < NCH; i++) {
                if (!used[i] && (!found || v[i] > bv)) { bv = v[i]; bi = i; found = true; }
            }
            used[bi] = true;
            g_idx[k] = bi;
        }
    }
}

// Gather: 512 threads x 8 float4 per block; 4096 float4 per block.
// per_ch = 147456 float4 -> 36 blocks per output channel, 288 blocks total.
__global__ __launch_bounds__(512) void gather_kernel(const float* __restrict__ x,
                                                     float* __restrict__ out) {
    const int per_ch_v = CH_STRIDE / 4;          // 147456
    const int chunks_per_ch = per_ch_v / 4096;   // 36
    int k = blockIdx.x / chunks_per_ch;
    int chunk = blockIdx.x - k * chunks_per_ch;
    int c = g_idx[k];
    const float4* src = reinterpret_cast<const float4*>(x + (size_t)c * CH_STRIDE);
    float4* dst = reinterpret_cast<float4*>(out) + (size_t)k * per_ch_v;
    int base = chunk * 4096 + threadIdx.x;
    float4 v[8];
#pragma unroll
    for (int i = 0; i < 8; i++) v[i] = src[base + i * 512];
#pragma unroll
    for (int i = 0; i < 8; i++) dst[base + i * 512] = v[i];
}

extern "C" void kernel_launch(void* const* d_in, const int* in_sizes, int n_in,
                              void* d_out, int out_size) {
    const float* x = (const float*)d_in[0];
    float* out = (float*)d_out;

    cudaFuncSetAttribute(harris_kernel,
                         cudaFuncAttributeMaxDynamicSharedMemorySize, SH_BYTES);

    zero_kernel<<<1, 32>>>();
    dim3 grid(3, 3, NCH * 2);
    harris_kernel<<<grid, 512, SH_BYTES>>>(x);
    topk_kernel<<<1, 1>>>();
    const int gather_blocks = KOUT * ((CH_STRIDE / 4) / 4096);  // 288
    gather_kernel<<<gather_blocks, 512>>>(x, out);
}

// round 4
// speedup vs baseline: 1.1338x; 1.1338x over previous
#include <cuda_runtime.h>
#include <cuda_bf16.h>
#include <cstddef>

// Problem constants
#define NCH 16
#define ND  64
#define NH  96
#define NW  96
#define PLANE (NH*NW)            // 9216
#define CH_STRIDE (ND*NH*NW)     // 589824
#define KOUT 8

typedef unsigned long long u64;

// ---- f32x2 packed helpers (sm_103a) ----
__device__ __forceinline__ u64 pk2(float a, float b) {
    u64 r; asm("mov.b64 %0,{%1,%2};" : "=l"(r) : "f"(a), "f"(b)); return r;
}
__device__ __forceinline__ void upk2(u64 v, float& a, float& b) {
    asm("mov.b64 {%0,%1},%2;" : "=f"(a), "=f"(b) : "l"(v));
}
__device__ __forceinline__ u64 add2(u64 a, u64 b) {
    u64 r; asm("add.rn.f32x2 %0,%1,%2;" : "=l"(r) : "l"(a), "l"(b)); return r;
}
__device__ __forceinline__ u64 mul2(u64 a, u64 b) {
    u64 r; asm("mul.rn.f32x2 %0,%1,%2;" : "=l"(r) : "l"(a), "l"(b)); return r;
}
__device__ __forceinline__ u64 fma2(u64 a, u64 b, u64 c) {
    u64 r; asm("fma.rn.f32x2 %0,%1,%2,%3;" : "=l"(r) : "l"(a), "l"(b), "l"(c)); return r;
}

__device__ double g_p[NCH];
__device__ int    g_idx[KOUT];

__global__ void zero_kernel() {
    if (threadIdx.x < NCH) g_p[threadIdx.x] = 0.0;
}

__global__ __launch_bounds__(512, 2) void harris_kernel(const float* __restrict__ x) {
    __shared__ float2 AB[36 * 38];        // (A, BZ) interleaved, row stride 38
    __shared__ float  GX[34 * 36];
    __shared__ float  GY[34 * 36];
    __shared__ float  GZ[34 * 36];
    __shared__ float  RED[16];

    const int tid   = threadIdx.x;
    const int c     = blockIdx.z >> 1;
    const int zhalf = blockIdx.z & 1;
    const int h0    = blockIdx.y * 32;
    const int w0    = blockIdx.x * 32;
    const float* xc = x + (size_t)c * CH_STRIDE;

    const int z0 = zhalf * 32;
    const int z1 = z0 + 32;
    const int s_begin = (z0 == 0) ? 0 : z0 - 1;
    const int s_end   = (z1 == ND) ? ND - 1 : z1;   // inclusive

    // ---- per-thread owned pixels of the 36x36 extended grid (up to 3) ----
    // k=0,1 always valid (tid, tid+512 < 1296); k=2 valid iff tid < 272.
    int offs[3];
#pragma unroll
    for (int k = 0; k < 3; k++) {
        int idx = tid + k * 512;
        if (idx < 36*36) {
            int i = idx / 36, j = idx % 36;
            int gh = h0 + i - 2, gw = w0 + j - 2;
            offs[k] = ((unsigned)gh < (unsigned)NH && (unsigned)gw < (unsigned)NW)
                      ? gh*NW + gw : -1;
        } else offs[k] = -1;
    }

    // x-depth ring: xm = x(t-1), x0r = x(t), where next st1 writes slice t
    float xm[3], x0r[3];
#pragma unroll
    for (int k = 0; k < 3; k++) {
        xm[k] = 0.f; x0r[k] = 0.f;
        if (offs[k] >= 0) {
            if (s_begin - 1 >= 0) xm[k] = xc[(size_t)(s_begin-1)*PLANE + offs[k]];
            x0r[k] = xc[(size_t)s_begin*PLANE + offs[k]];
        }
    }

    // fused-stage ownership: 2 vertical pixels (rows r0, r0+1), full-width col tw
    const int tw = tid & 31;
    const int r0 = (tid >> 5) * 2;

    // depth running sums, packed (px0, px1)
    u64 A1[6], A2[6];
    const u64 ZERO2 = pk2(0.f, 0.f);
#pragma unroll
    for (int k = 0; k < 6; k++) { A1[k] = ZERO2; A2[k] = ZERO2; }
    u64 hsum2 = ZERO2;
    const u64 C1v = pk2(1.f/19683.f, 1.f/19683.f);   // 1/27^3
    const u64 C2v = pk2(0.04f/729.f, 0.04f/729.f);   // k/27^2
    const u64 NEG1 = pk2(-1.f, -1.f);

#define SUB2(a, b) fma2((b), NEG1, (a))

#define DO_ST1(T) do {                                                         \
    int t_ = (T);                                                              \
    _Pragma("unroll")                                                          \
    for (int k = 0; k < 3; k++) {                                              \
        int idx = tid + k * 512;                                               \
        if (k < 2 || idx < 36*36) {                                            \
            float xpv = 0.f;                                                   \
            if (offs[k] >= 0 && t_ + 1 < ND)                                   \
                xpv = xc[(size_t)(t_+1)*PLANE + offs[k]];                      \
            int i = idx / 36, j = idx % 36;                                    \
            AB[i*38 + j] = make_float2(xm[k] + x0r[k] + xpv, xpv - xm[k]);     \
            xm[k] = x0r[k]; x0r[k] = xpv;                                      \
        }                                                                      \
    }                                                                          \
} while (0)

#define DO_ST2() do {                                                          \
    if (tid < 289) {                                                           \
        int i0 = (tid / 17) * 2, j0 = (tid % 17) * 2;                          \
        float Av[4][4], Bv[4][4];                                              \
        _Pragma("unroll")                                                      \
        for (int r = 0; r < 4; r++) {                                          \
            const float4* p = reinterpret_cast<const float4*>(AB + ((i0+r)*38 + j0)); \
            float4 u = p[0], v = p[1];                                         \
            Av[r][0]=u.x; Bv[r][0]=u.y; Av[r][1]=u.z; Bv[r][1]=u.w;            \
            Av[r][2]=v.x; Bv[r][2]=v.y; Av[r][3]=v.z; Bv[r][3]=v.w;            \
        }                                                                      \
        float hd[4][2], h121[4][2], rs[4][2];                                  \
        _Pragma("unroll")                                                      \
        for (int r = 0; r < 4; r++) {                                          \
            hd[r][0]   = Av[r][2] - Av[r][0];                                  \
            hd[r][1]   = Av[r][3] - Av[r][1];                                  \
            h121[r][0] = Av[r][0] + 2.f*Av[r][1] + Av[r][2];                   \
            h121[r][1] = Av[r][1] + 2.f*Av[r][2] + Av[r][3];                   \
            rs[r][0]   = Bv[r][0] + Bv[r][1] + Bv[r][2];                       \
            rs[r][1]   = Bv[r][1] + Bv[r][2] + Bv[r][3];                       \
        }                                                                      \
        _Pragma("unroll")                                                      \
        for (int rr = 0; rr < 2; rr++) {                                       \
            int go = (i0+rr)*36 + j0;                                          \
            float gx0 = hd[rr][0] + 2.f*hd[rr+1][0] + hd[rr+2][0];             \
            float gx1 = hd[rr][1] + 2.f*hd[rr+1][1] + hd[rr+2][1];             \
            float gy0 = h121[rr+2][0] - h121[rr][0];                           \
            float gy1 = h121[rr+2][1] - h121[rr][1];                           \
            float gz0 = rs[rr][0] + rs[rr+1][0] + rs[rr+2][0];                 \
            float gz1 = rs[rr][1] + rs[rr+1][1] + rs[rr+2][1];                 \
            *reinterpret_cast<float2*>(GX + go) = make_float2(gx0, gx1);       \
            *reinterpret_cast<float2*>(GY + go) = make_float2(gy0, gy1);       \
            *reinterpret_cast<float2*>(GZ + go) = make_float2(gz0, gz1);       \
        }                                                                      \
    }                                                                          \
} while (0)

    // ---- prologue: st1(s_begin), st2(s_begin) ----
    DO_ST1(s_begin);
    __syncthreads();
    DO_ST2();
    __syncthreads();

    // ================= main loop =================
    for (int s = s_begin; s <= s_end; s++) {
        const bool more = (s < s_end);

        // ---------- phase A: prefetch x(s+2), fused st3+4(s), st1-store(s+1) ----------
        float xpv[3];
        if (more) {
#pragma unroll
            for (int k = 0; k < 3; k++) {
                xpv[k] = 0.f;
                if (offs[k] >= 0 && s + 2 < ND)
                    xpv[k] = xc[(size_t)(s+2)*PLANE + offs[k]];
            }
        }

        // fused stage3+4 on slice s: recompute rowP from G, depth accum, harris
        {
            float c0[6], c1[6];
#pragma unroll
            for (int k = 0; k < 6; k++) { c0[k] = 0.f; c1[k] = 0.f; }
#pragma unroll
            for (int ri = 0; ri < 4; ri++) {
                int b = (r0 + ri) * 36 + tw;
                float X0 = GX[b], X1 = GX[b+1], X2 = GX[b+2];
                float Y0 = GY[b], Y1 = GY[b+1], Y2 = GY[b+2];
                float Z0 = GZ[b], Z1 = GZ[b+1], Z2 = GZ[b+2];
                float pxx = fmaf(X0,X0, fmaf(X1,X1, X2*X2));
                float pyy = fmaf(Y0,Y0, fmaf(Y1,Y1, Y2*Y2));
                float pzz = fmaf(Z0,Z0, fmaf(Z1,Z1, Z2*Z2));
                float pxy = fmaf(X0,Y0, fmaf(X1,Y1, X2*Y2));
                float pxz = fmaf(X0,Z0, fmaf(X1,Z1, X2*Z2));
                float pyz = fmaf(Y0,Z0, fmaf(Y1,Z1, Y2*Z2));
                if (ri < 3) {
                    c0[0] += pxx; c0[1] += pyy; c0[2] += pzz;
                    c0[3] += pxy; c0[4] += pxz; c0[5] += pyz;
                }
                if (ri > 0) {
                    c1[0] += pxx; c1[1] += pyy; c1[2] += pzz;
                    c1[3] += pxy; c1[4] += pxz; c1[5] += pyz;
                }
            }
            u64 cur[6];
#pragma unroll
            for (int k = 0; k < 6; k++) cur[k] = pk2(c0[k], c1[k]);

            int d = s - 1;
            if (d >= z0) {
                u64 sxx = add2(A2[0], cur[0]);
                u64 syy = add2(A2[1], cur[1]);
                u64 szz = add2(A2[2], cur[2]);
                u64 sxy = add2(A2[3], cur[3]);
                u64 sxz = add2(A2[4], cur[4]);
                u64 syz = add2(A2[5], cur[5]);
                u64 m1  = SUB2(mul2(syy, szz), mul2(syz, syz));
                u64 m2  = SUB2(mul2(sxy, szz), mul2(syz, sxz));
                u64 m3  = SUB2(mul2(sxy, syz), mul2(syy, sxz));
                u64 det = SUB2(fma2(sxx, m1, mul2(sxz, m3)), mul2(sxy, m2));
                u64 tr  = add2(add2(sxx, syy), szz);
                u64 h   = SUB2(mul2(det, C1v), mul2(mul2(tr, tr), C2v));
                hsum2 = add2(hsum2, h);
            }
#pragma unroll
            for (int k = 0; k < 6; k++) { A2[k] = add2(A1[k], cur[k]); A1[k] = cur[k]; }
        }

        // st1 stores for slice s+1 (consumes prefetched xpv)
        if (more) {
#pragma unroll
            for (int k = 0; k < 3; k++) {
                int idx = tid + k * 512;
                if (k < 2 || idx < 36*36) {
                    int i = idx / 36, j = idx % 36;
                    AB[i*38 + j] = make_float2(xm[k] + x0r[k] + xpv[k], xpv[k] - xm[k]);
                    xm[k] = x0r[k]; x0r[k] = xpv[k];
                }
            }
        }
        __syncthreads();

        // ---------- phase B: st2(s+1): AB -> G ----------
        if (more) {
            DO_ST2();
        }
        __syncthreads();
    }

    // tail: output depth ND-1 (slice at ND contributes 0)
    if (z1 == ND) {
        u64 sxx = A2[0], syy = A2[1], szz = A2[2];
        u64 sxy = A2[3], sxz = A2[4], syz = A2[5];
        u64 m1  = SUB2(mul2(syy, szz), mul2(syz, syz));
        u64 m2  = SUB2(mul2(sxy, szz), mul2(syz, sxz));
        u64 m3  = SUB2(mul2(sxy, syz), mul2(syy, sxz));
        u64 det = SUB2(fma2(sxx, m1, mul2(sxz, m3)), mul2(sxy, m2));
        u64 tr  = add2(add2(sxx, syy), szz);
        u64 h   = SUB2(mul2(det, C1v), mul2(mul2(tr, tr), C2v));
        hsum2 = add2(hsum2, h);
    }

    // ---- reduction ----
    float ha, hb;
    upk2(hsum2, ha, hb);
    float hsum = ha + hb;
#pragma unroll
    for (int o = 16; o > 0; o >>= 1)
        hsum += __shfl_down_sync(0xffffffffu, hsum, o);
    if ((tid & 31) == 0) RED[tid >> 5] = hsum;
    __syncthreads();
    if (tid < 32) {
        float v = (tid < 16) ? RED[tid] : 0.f;
#pragma unroll
        for (int o = 8; o > 0; o >>= 1)
            v += __shfl_down_sync(0xffffffffu, v, o);
        if (tid == 0) atomicAdd(&g_p[c], (double)v);
    }
#undef SUB2
#undef DO_ST1
#undef DO_ST2
}

__global__ void topk_kernel() {
    if (threadIdx.x == 0 && blockIdx.x == 0) {
        double v[NCH];
        bool used[NCH];
        for (int i = 0; i < NCH; i++) { v[i] = g_p[i]; used[i] = false; }
        for (int k = 0; k < KOUT; k++) {
            int bi = 0; double bv = -1e300; bool found = false;
            for (int i = 0; i < NCH; i++) {
                if (!used[i] && (!found || v[i] > bv)) { bv = v[i]; bi = i; found = true; }
            }
            used[bi] = true;
            g_idx[k] = bi;
        }
    }
}

// Gather: 512 threads x 8 float4 per block; 288 blocks.
__global__ __launch_bounds__(512) void gather_kernel(const float* __restrict__ x,
                                                     float* __restrict__ out) {
    const int per_ch_v = CH_STRIDE / 4;          // 147456
    const int chunks_per_ch = per_ch_v / 4096;   // 36
    int k = blockIdx.x / chunks_per_ch;
    int chunk = blockIdx.x - k * chunks_per_ch;
    int c = g_idx[k];
    const float4* src = reinterpret_cast<const float4*>(x + (size_t)c * CH_STRIDE);
    float4* dst = reinterpret_cast<float4*>(out) + (size_t)k * per_ch_v;
    int base = chunk * 4096 + threadIdx.x;
    float4 v[8];
#pragma unroll
    for (int i = 0; i < 8; i++) v[i] = src[base + i * 512];
#pragma unroll
    for (int i = 0; i < 8; i++) dst[base + i * 512] = v[i];
}

extern "C" void kernel_launch(void* const* d_in, const int* in_sizes, int n_in,
                              void* d_out, int out_size) {
    const float* x = (const float*)d_in[0];
    float* out = (float*)d_out;

    zero_kernel<<<1, 32>>>();
    dim3 grid(3, 3, NCH * 2);
    harris_kernel<<<grid, 512>>>(x);
    topk_kernel<<<1, 1>>>();
    const int gather_blocks = KOUT * ((CH_STRIDE / 4) / 4096);  // 288
    gather_kernel<<<gather_blocks, 512>>>(x, out);
}